// round 9
// baseline (speedup 1.0000x reference)
#include <cuda_runtime.h>
#include <cuda_bf16.h>
#include <cstdint>

// Problem constants
#define NB  4        // batch
#define NN  4096     // sequence (64*64)
#define NC  128      // channels
#define ND  16       // qk head dim

__device__ __forceinline__ uint32_t smem_u32(const void* p) {
    uint32_t a;
    asm("{ .reg .u64 tmp; cvta.to.shared.u64 tmp, %1; cvt.u32.u64 %0, tmp; }"
        : "=r"(a) : "l"(p));
    return a;
}

// ---- warp MMA primitives (plain PTX, valid on sm_100 non-a) ----
__device__ __forceinline__ void mma16816(float* c, const uint32_t* a,
                                         uint32_t b0, uint32_t b1) {
    asm volatile(
        "mma.sync.aligned.m16n8k16.row.col.f32.bf16.bf16.f32 "
        "{%0,%1,%2,%3}, {%4,%5,%6,%7}, {%8,%9}, {%0,%1,%2,%3};"
        : "+f"(c[0]), "+f"(c[1]), "+f"(c[2]), "+f"(c[3])
        : "r"(a[0]), "r"(a[1]), "r"(a[2]), "r"(a[3]), "r"(b0), "r"(b1));
}
#define LDSM_X4(r0,r1,r2,r3,addr) \
    asm volatile("ldmatrix.sync.aligned.m8n8.x4.shared.b16 {%0,%1,%2,%3}, [%4];" \
        : "=r"(r0), "=r"(r1), "=r"(r2), "=r"(r3) : "r"(addr))
#define LDSM_X4_T(r0,r1,r2,r3,addr) \
    asm volatile("ldmatrix.sync.aligned.m8n8.x4.trans.shared.b16 {%0,%1,%2,%3}, [%4];" \
        : "=r"(r0), "=r"(r1), "=r"(r2), "=r"(r3) : "r"(addr))

#define CP_ASYNC16(dst, src) \
    asm volatile("cp.async.cg.shared.global [%0], [%1], 16;" :: "r"(dst), "l"(src) : "memory")
#define CP_COMMIT() asm volatile("cp.async.commit_group;" ::: "memory")
#define CP_WAIT1()  asm volatile("cp.async.wait_group 1;" ::: "memory")
#define CP_WAIT0()  asm volatile("cp.async.wait_group 0;" ::: "memory")

// =====================================================================
// Device scratch
// =====================================================================
__device__ __nv_bfloat16 g_Qb[NB * NN * ND];            // queries = x @ Wk (bf16)
__device__ __nv_bfloat16 g_Kb[NB * NN * ND];            // keys    = x @ Wq (bf16)
__device__ __nv_bfloat16 g_V [(size_t)NB * NN * NC];    // values  = x @ Wv (bf16) [b][n][c]

// =====================================================================
// Projection GEMM (HMMA): [16384 x 128] x [128 x 160] -> V | Kb | Qb
// (unchanged from round 6 — measured ~1us)
// =====================================================================
#define PJP 272
#define WP  336
#define PSM_X 0
#define PSM_W (128 * PJP)
#define PROJ_SMEM_BYTES (PSM_W + 128 * WP)      // 77824

__global__ __launch_bounds__(256, 1) void proj_mma_kernel(
        const float* __restrict__ x,
        const float* __restrict__ Wq,
        const float* __restrict__ Wk,
        const float* __restrict__ Wv) {
    extern __shared__ char smem[];
    const uint32_t sb = smem_u32(smem);
    const int t = threadIdx.x;
    const int w = t >> 5, lane = t & 31;
    const int row0 = blockIdx.x * 128;

    {
        const float4* wv4 = (const float4*)Wv;
        #pragma unroll
        for (int i = 0; i < 16; i++) {
            int idx = t + i * 256;
            int c = idx >> 5, e4 = idx & 31;
            float4 v = wv4[idx];
            uint2 p;
            asm("cvt.rn.bf16x2.f32 %0, %1, %2;" : "=r"(p.x) : "f"(v.y), "f"(v.x));
            asm("cvt.rn.bf16x2.f32 %0, %1, %2;" : "=r"(p.y) : "f"(v.w), "f"(v.z));
            *(uint2*)(smem + PSM_W + c * WP + e4 * 8) = p;
        }
        const float4* wq4 = (const float4*)Wq;
        const float4* wk4 = (const float4*)Wk;
        #pragma unroll
        for (int i = 0; i < 2; i++) {
            int idx = t + i * 256;
            int c = idx >> 2, d4 = idx & 3;
            float4 q = wq4[idx];
            uint2 p;
            asm("cvt.rn.bf16x2.f32 %0, %1, %2;" : "=r"(p.x) : "f"(q.y), "f"(q.x));
            asm("cvt.rn.bf16x2.f32 %0, %1, %2;" : "=r"(p.y) : "f"(q.w), "f"(q.z));
            *(uint2*)(smem + PSM_W + c * WP + 256 + d4 * 8) = p;
            float4 k = wk4[idx];
            asm("cvt.rn.bf16x2.f32 %0, %1, %2;" : "=r"(p.x) : "f"(k.y), "f"(k.x));
            asm("cvt.rn.bf16x2.f32 %0, %1, %2;" : "=r"(p.y) : "f"(k.w), "f"(k.z));
            *(uint2*)(smem + PSM_W + c * WP + 288 + d4 * 8) = p;
        }
    }
    {
        const float4* src = (const float4*)(x + (size_t)row0 * NC);
        #pragma unroll
        for (int i = 0; i < 16; i++) {
            int idx = t + i * 256;
            int r = idx >> 5, ch = idx & 31;
            float4 v = src[idx];
            uint2 p;
            asm("cvt.rn.bf16x2.f32 %0, %1, %2;" : "=r"(p.x) : "f"(v.y), "f"(v.x));
            asm("cvt.rn.bf16x2.f32 %0, %1, %2;" : "=r"(p.y) : "f"(v.w), "f"(v.z));
            *(uint2*)(smem + PSM_X + r * PJP + ch * 8) = p;
        }
    }
    __syncthreads();

    float C[20][4];
    #pragma unroll
    for (int i = 0; i < 20; i++)
        #pragma unroll
        for (int j = 0; j < 4; j++) C[i][j] = 0.f;

    const uint32_t a_base = sb + PSM_X + (uint32_t)(w * 16 + (lane & 15)) * PJP
                          + (uint32_t)((lane >> 4) * 16);
    const uint32_t b_base = sb + PSM_W
                          + (uint32_t)((lane & 7) + ((lane & 8) ? 8 : 0)) * WP
                          + (uint32_t)((lane & 16) ? 16 : 0);

    #pragma unroll
    for (int k = 0; k < 8; k++) {
        uint32_t a[4];
        LDSM_X4(a[0], a[1], a[2], a[3], a_base + (uint32_t)k * 32);
        #pragma unroll
        for (int np = 0; np < 10; np++) {
            uint32_t b0, b1, b2, b3;
            LDSM_X4_T(b0, b1, b2, b3,
                      b_base + (uint32_t)k * (16 * WP) + (uint32_t)np * 32);
            mma16816(C[2*np],     a, b0, b1);
            mma16816(C[2*np + 1], a, b2, b3);
        }
    }

    const int r0 = row0 + w * 16 + (lane >> 2);
    const int r1 = r0 + 8;
    #pragma unroll
    for (int nt = 0; nt < 20; nt++) {
        const int c = nt * 8 + 2 * (lane & 3);
        uint32_t p0, p1;
        asm("cvt.rn.bf16x2.f32 %0, %1, %2;" : "=r"(p0) : "f"(C[nt][1]), "f"(C[nt][0]));
        asm("cvt.rn.bf16x2.f32 %0, %1, %2;" : "=r"(p1) : "f"(C[nt][3]), "f"(C[nt][2]));
        if (c < 128) {
            *(uint32_t*)(g_V + (size_t)r0 * NC + c) = p0;
            *(uint32_t*)(g_V + (size_t)r1 * NC + c) = p1;
        } else if (c < 144) {
            const int d = c - 128;
            *(uint32_t*)(g_Kb + (size_t)r0 * ND + d) = p0;
            *(uint32_t*)(g_Kb + (size_t)r1 * ND + d) = p1;
        } else {
            const int d = c - 144;
            *(uint32_t*)(g_Qb + (size_t)r0 * ND + d) = p0;
            *(uint32_t*)(g_Qb + (size_t)r1 * ND + d) = p1;
        }
    }
}

// =====================================================================
// Flash attention (HMMA), 8 warps x 16 query rows, FUSED cross-tile
// software pipeline. Key insight: QK has ONE k-step (ND=16), so each S
// n8-pair completes after a single MMA. Per kk step we do:
//   LDSM K(kk) -> 2x MMA S-pair -> exp/pack -> pa[cur][kk]
//   || PV(t-1) step kk (8x LDSM_T + 16x MMA) using pa[prv][kk]
// No full S array (8 transient regs vs 64) -> no spills; MUFU/cvt chain
// hides under the PV HMMA stream.
// V triple-buffered (PV reads (t-1)%3 while cp.async writes (t+1)%3);
// K double-buffered; P fragments double-buffered in registers.
// =====================================================================
#define QKP 48                         // Q/K smem row pitch (bytes)
#define VP  272                        // V smem row pitch (bytes)
#define SM_Q  0
#define SM_K0 6144
#define SM_V0 18432
#define K_BUF_BYTES 6144
#define V_BUF_BYTES 34816
#define ATTN_SMEM_BYTES (SM_V0 + 3*V_BUF_BYTES)   // 122880

__global__ __launch_bounds__(256, 1) void attn_mma_kernel(
        const float* __restrict__ x,
        const float* __restrict__ gammap,
        float* __restrict__ out) {
    extern __shared__ char smem[];
    const uint32_t sb = smem_u32(smem);
    const int t = threadIdx.x;
    const int w = t >> 5, lane = t & 31;
    const int b = blockIdx.y;
    const int m0 = blockIdx.x * 128;

    const __nv_bfloat16* qbase = g_Qb + (size_t)b * NN * ND;
    const __nv_bfloat16* kbase = g_Kb + (size_t)b * NN * ND;
    const __nv_bfloat16* vbase = g_V  + (size_t)b * NN * NC;

    // ---- stage Q tile [128 x 16] (pitch 48B) ----
    {
        int r = t >> 1, c2 = t & 1;
        const uint4* src = (const uint4*)(qbase + (size_t)(m0 + r) * ND) + c2;
        *(uint4*)(smem + SM_Q + r * QKP + c2 * 16) = *src;
    }

    // ---- prefetch tile 0 (K buf 0, V buf 0) ----
    {
        int r = t >> 1, c2 = t & 1;
        CP_ASYNC16(sb + SM_K0 + r * QKP + c2 * 16,
                   (const char*)(kbase) + (size_t)r * 32 + c2 * 16);
        #pragma unroll
        for (int i = 0; i < 8; i++) {
            int idx = t + i * 256;
            int row = idx >> 4, vch = idx & 15;
            CP_ASYNC16(sb + SM_V0 + row * VP + vch * 16,
                       (const char*)(vbase) + (size_t)row * 256 + vch * 16);
        }
    }
    CP_COMMIT();
    __syncthreads();

    // ---- Q A-fragment (constant for whole kernel) ----
    uint32_t qa[4];
    {
        uint32_t addr = sb + SM_Q + (uint32_t)(w * 16 + (lane & 15)) * QKP
                      + (uint32_t)((lane >> 4) * 16);
        LDSM_X4(qa[0], qa[1], qa[2], qa[3], addr);
    }

    // per-lane ldmatrix fragment base offsets
    const uint32_t kfrag = (uint32_t)((lane & 7) + ((lane & 16) ? 8 : 0)) * QKP
                         + (uint32_t)((lane & 8) ? 16 : 0);
    const uint32_t vfrag = (uint32_t)((lane & 7) + ((lane & 8) ? 8 : 0)) * VP
                         + (uint32_t)((lane & 16) ? 16 : 0);

    float O[16][4];
    #pragma unroll
    for (int i = 0; i < 16; i++)
        #pragma unroll
        for (int j = 0; j < 4; j++) O[i][j] = 0.f;
    float lsum0 = 0.f, lsum1 = 0.f;

    uint32_t pa[2][8][4];              // P fragments, double-buffered by tile parity
    int vprev_idx = 0;                 // V buffer index of previous tile

    for (int tile = 0; tile < 32; ++tile) {
        // prefetch next tile: K buf (t+1)%2, V buf (t+1)%3
        if (tile < 31) {
            const int kb_ = (tile + 1) & 1;
            const int vb_ = (tile + 1) % 3;
            const size_t n0n = (size_t)(tile + 1) * 128;
            int r = t >> 1, c2 = t & 1;
            CP_ASYNC16(sb + SM_K0 + kb_ * K_BUF_BYTES + r * QKP + c2 * 16,
                       (const char*)(kbase) + (n0n + r) * 32 + c2 * 16);
            #pragma unroll
            for (int i = 0; i < 8; i++) {
                int idx = t + i * 256;
                int row = idx >> 4, vch = idx & 15;
                CP_ASYNC16(sb + SM_V0 + vb_ * V_BUF_BYTES + row * VP + vch * 16,
                           (const char*)(vbase) + (n0n + row) * 256 + vch * 16);
            }
            CP_COMMIT();
            CP_WAIT1();
        } else {
            CP_WAIT0();
        }
        __syncthreads();

        const uint32_t kbuf  = sb + SM_K0 + (tile & 1) * K_BUF_BYTES;
        const uint32_t vprev = sb + SM_V0 + vprev_idx * V_BUF_BYTES;
        const int cur = tile & 1, prv = cur ^ 1;

        // ---- fused QK -> exp -> pack, interleaved with PV(t-1) ----
        #pragma unroll
        for (int kk = 0; kk < 8; kk++) {
            // QK for this kk: one K fragment, S-pair completes immediately
            float S0[4] = {0.f, 0.f, 0.f, 0.f};
            float S1[4] = {0.f, 0.f, 0.f, 0.f};
            {
                uint32_t kb0, kb1, kb2, kb3;
                LDSM_X4(kb0, kb1, kb2, kb3, kbuf + kfrag + (uint32_t)kk * (16 * QKP));
                mma16816(S0, qa, kb0, kb1);
                mma16816(S1, qa, kb2, kb3);
            }
            // PV step kk of PREVIOUS tile (independent; hides exp latency)
            if (tile > 0) {
                #pragma unroll
                for (int cp = 0; cp < 8; cp++) {
                    uint32_t vb0, vb1, vb2, vb3;
                    LDSM_X4_T(vb0, vb1, vb2, vb3,
                              vprev + vfrag + (uint32_t)kk * (16 * VP) + (uint32_t)cp * 32);
                    mma16816(O[2*cp],     pa[prv][kk], vb0, vb1);
                    mma16816(O[2*cp + 1], pa[prv][kk], vb2, vb3);
                }
            }
            // exp + pack -> pa[cur][kk]
            {
                float e0 = __expf(S0[0]), e1 = __expf(S0[1]);
                float e2 = __expf(S0[2]), e3 = __expf(S0[3]);
                float e4 = __expf(S1[0]), e5 = __expf(S1[1]);
                float e6 = __expf(S1[2]), e7 = __expf(S1[3]);
                lsum0 += e0 + e1 + e4 + e5;
                lsum1 += e2 + e3 + e6 + e7;
                asm("cvt.rn.bf16x2.f32 %0, %1, %2;" : "=r"(pa[cur][kk][0]) : "f"(e1), "f"(e0));
                asm("cvt.rn.bf16x2.f32 %0, %1, %2;" : "=r"(pa[cur][kk][1]) : "f"(e3), "f"(e2));
                asm("cvt.rn.bf16x2.f32 %0, %1, %2;" : "=r"(pa[cur][kk][2]) : "f"(e5), "f"(e4));
                asm("cvt.rn.bf16x2.f32 %0, %1, %2;" : "=r"(pa[cur][kk][3]) : "f"(e7), "f"(e6));
            }
        }
        vprev_idx = tile % 3;
        __syncthreads();
    }

    // ---- tail: PV for tile 31 (pa[1], V buf 31%3 = 1) ----
    {
        const uint32_t vlast = sb + SM_V0 + (31 % 3) * V_BUF_BYTES;
        #pragma unroll
        for (int kk = 0; kk < 8; kk++) {
            #pragma unroll
            for (int cp = 0; cp < 8; cp++) {
                uint32_t vb0, vb1, vb2, vb3;
                LDSM_X4_T(vb0, vb1, vb2, vb3,
                          vlast + vfrag + (uint32_t)kk * (16 * VP) + (uint32_t)cp * 32);
                mma16816(O[2*cp],     pa[1][kk], vb0, vb1);
                mma16816(O[2*cp + 1], pa[1][kk], vb2, vb3);
            }
        }
    }

    // ---- softmax denominators: reduce across the 4-lane quad ----
    lsum0 += __shfl_xor_sync(0xffffffffu, lsum0, 1);
    lsum0 += __shfl_xor_sync(0xffffffffu, lsum0, 2);
    lsum1 += __shfl_xor_sync(0xffffffffu, lsum1, 1);
    lsum1 += __shfl_xor_sync(0xffffffffu, lsum1, 2);
    const float inv0 = 1.0f / lsum0;
    const float inv1 = 1.0f / lsum1;
    const float gamma = *gammap;

    // ---- write out[b, c*4096 + m] = gamma*O/lsum + x ----
    const int r0 = m0 + w * 16 + (lane >> 2);
    const int r1 = r0 + 8;
    const size_t bbase = (size_t)b * (NN * NC);
    #pragma unroll
    for (int nt = 0; nt < 16; nt++) {
        const int c = nt * 8 + 2 * (lane & 3);
        const size_t i00 = bbase + (size_t)c * NN + r0;
        out[i00]        = gamma * (O[nt][0] * inv0) + x[i00];
        out[i00 + NN]   = gamma * (O[nt][1] * inv0) + x[i00 + NN];
        const size_t i10 = bbase + (size_t)c * NN + r1;
        out[i10]        = gamma * (O[nt][2] * inv1) + x[i10];
        out[i10 + NN]   = gamma * (O[nt][3] * inv1) + x[i10 + NN];
    }
}

// =====================================================================
extern "C" void kernel_launch(void* const* d_in, const int* in_sizes, int n_in,
                              void* d_out, int out_size) {
    (void)in_sizes; (void)n_in; (void)out_size;
    const float* x     = (const float*)d_in[0];
    const float* Wq    = (const float*)d_in[1];
    const float* Wk    = (const float*)d_in[2];
    const float* Wv    = (const float*)d_in[3];
    const float* gamma = (const float*)d_in[4];
    float* out = (float*)d_out;

    cudaFuncSetAttribute((const void*)proj_mma_kernel,
                         cudaFuncAttributeMaxDynamicSharedMemorySize, PROJ_SMEM_BYTES);
    cudaFuncSetAttribute((const void*)attn_mma_kernel,
                         cudaFuncAttributeMaxDynamicSharedMemorySize, ATTN_SMEM_BYTES);

    proj_mma_kernel<<<128, 256, PROJ_SMEM_BYTES>>>(x, Wq, Wk, Wv);
    attn_mma_kernel<<<dim3(32, 4), 256, ATTN_SMEM_BYTES>>>(x, gamma, out);
}

// round 12
// speedup vs baseline: 1.2714x; 1.2714x over previous
#include <cuda_runtime.h>
#include <cuda_bf16.h>
#include <cstdint>

// Problem constants
#define NB  4        // batch
#define NN  4096     // sequence (64*64)
#define NC  128      // channels
#define ND  16       // qk head dim

__device__ __forceinline__ uint32_t smem_u32(const void* p) {
    uint32_t a;
    asm("{ .reg .u64 tmp; cvta.to.shared.u64 tmp, %1; cvt.u32.u64 %0, tmp; }"
        : "=r"(a) : "l"(p));
    return a;
}

// ---- warp MMA primitives (plain PTX, valid on sm_100 non-a) ----
__device__ __forceinline__ void mma16816(float* c, const uint32_t* a,
                                         uint32_t b0, uint32_t b1) {
    asm volatile(
        "mma.sync.aligned.m16n8k16.row.col.f32.bf16.bf16.f32 "
        "{%0,%1,%2,%3}, {%4,%5,%6,%7}, {%8,%9}, {%0,%1,%2,%3};"
        : "+f"(c[0]), "+f"(c[1]), "+f"(c[2]), "+f"(c[3])
        : "r"(a[0]), "r"(a[1]), "r"(a[2]), "r"(a[3]), "r"(b0), "r"(b1));
}
#define LDSM_X4(r0,r1,r2,r3,addr) \
    asm volatile("ldmatrix.sync.aligned.m8n8.x4.shared.b16 {%0,%1,%2,%3}, [%4];" \
        : "=r"(r0), "=r"(r1), "=r"(r2), "=r"(r3) : "r"(addr))
#define LDSM_X4_T(r0,r1,r2,r3,addr) \
    asm volatile("ldmatrix.sync.aligned.m8n8.x4.trans.shared.b16 {%0,%1,%2,%3}, [%4];" \
        : "=r"(r0), "=r"(r1), "=r"(r2), "=r"(r3) : "r"(addr))

#define CP_ASYNC16(dst, src) \
    asm volatile("cp.async.cg.shared.global [%0], [%1], 16;" :: "r"(dst), "l"(src) : "memory")
#define CP_COMMIT() asm volatile("cp.async.commit_group;" ::: "memory")
#define CP_WAIT1()  asm volatile("cp.async.wait_group 1;" ::: "memory")
#define CP_WAIT0()  asm volatile("cp.async.wait_group 0;" ::: "memory")

// =====================================================================
// Device scratch
// =====================================================================
__device__ __nv_bfloat16 g_Qb[NB * NN * ND];            // queries = x @ Wk (bf16)
__device__ __nv_bfloat16 g_Kb[NB * NN * ND];            // keys    = x @ Wq (bf16)
__device__ __nv_bfloat16 g_V [(size_t)NB * NN * NC];    // values  = x @ Wv (bf16) [b][n][c]

// =====================================================================
// Projection GEMM (HMMA): [16384 x 128] x [128 x 160] -> V | Kb | Qb
// (unchanged from round 6 — ~1us)
// =====================================================================
#define PJP 272
#define WP  336
#define PSM_X 0
#define PSM_W (128 * PJP)
#define PROJ_SMEM_BYTES (PSM_W + 128 * WP)      // 77824

__global__ __launch_bounds__(256, 1) void proj_mma_kernel(
        const float* __restrict__ x,
        const float* __restrict__ Wq,
        const float* __restrict__ Wk,
        const float* __restrict__ Wv) {
    extern __shared__ char smem[];
    const uint32_t sb = smem_u32(smem);
    const int t = threadIdx.x;
    const int w = t >> 5, lane = t & 31;
    const int row0 = blockIdx.x * 128;

    {
        const float4* wv4 = (const float4*)Wv;
        #pragma unroll
        for (int i = 0; i < 16; i++) {
            int idx = t + i * 256;
            int c = idx >> 5, e4 = idx & 31;
            float4 v = wv4[idx];
            uint2 p;
            asm("cvt.rn.bf16x2.f32 %0, %1, %2;" : "=r"(p.x) : "f"(v.y), "f"(v.x));
            asm("cvt.rn.bf16x2.f32 %0, %1, %2;" : "=r"(p.y) : "f"(v.w), "f"(v.z));
            *(uint2*)(smem + PSM_W + c * WP + e4 * 8) = p;
        }
        const float4* wq4 = (const float4*)Wq;
        const float4* wk4 = (const float4*)Wk;
        #pragma unroll
        for (int i = 0; i < 2; i++) {
            int idx = t + i * 256;
            int c = idx >> 2, d4 = idx & 3;
            float4 q = wq4[idx];
            uint2 p;
            asm("cvt.rn.bf16x2.f32 %0, %1, %2;" : "=r"(p.x) : "f"(q.y), "f"(q.x));
            asm("cvt.rn.bf16x2.f32 %0, %1, %2;" : "=r"(p.y) : "f"(q.w), "f"(q.z));
            *(uint2*)(smem + PSM_W + c * WP + 256 + d4 * 8) = p;
            float4 k = wk4[idx];
            asm("cvt.rn.bf16x2.f32 %0, %1, %2;" : "=r"(p.x) : "f"(k.y), "f"(k.x));
            asm("cvt.rn.bf16x2.f32 %0, %1, %2;" : "=r"(p.y) : "f"(k.w), "f"(k.z));
            *(uint2*)(smem + PSM_W + c * WP + 288 + d4 * 8) = p;
        }
    }
    {
        const float4* src = (const float4*)(x + (size_t)row0 * NC);
        #pragma unroll
        for (int i = 0; i < 16; i++) {
            int idx = t + i * 256;
            int r = idx >> 5, ch = idx & 31;
            float4 v = src[idx];
            uint2 p;
            asm("cvt.rn.bf16x2.f32 %0, %1, %2;" : "=r"(p.x) : "f"(v.y), "f"(v.x));
            asm("cvt.rn.bf16x2.f32 %0, %1, %2;" : "=r"(p.y) : "f"(v.w), "f"(v.z));
            *(uint2*)(smem + PSM_X + r * PJP + ch * 8) = p;
        }
    }
    __syncthreads();

    float C[20][4];
    #pragma unroll
    for (int i = 0; i < 20; i++)
        #pragma unroll
        for (int j = 0; j < 4; j++) C[i][j] = 0.f;

    const uint32_t a_base = sb + PSM_X + (uint32_t)(w * 16 + (lane & 15)) * PJP
                          + (uint32_t)((lane >> 4) * 16);
    const uint32_t b_base = sb + PSM_W
                          + (uint32_t)((lane & 7) + ((lane & 8) ? 8 : 0)) * WP
                          + (uint32_t)((lane & 16) ? 16 : 0);

    #pragma unroll
    for (int k = 0; k < 8; k++) {
        uint32_t a[4];
        LDSM_X4(a[0], a[1], a[2], a[3], a_base + (uint32_t)k * 32);
        #pragma unroll
        for (int np = 0; np < 10; np++) {
            uint32_t b0, b1, b2, b3;
            LDSM_X4_T(b0, b1, b2, b3,
                      b_base + (uint32_t)k * (16 * WP) + (uint32_t)np * 32);
            mma16816(C[2*np],     a, b0, b1);
            mma16816(C[2*np + 1], a, b2, b3);
        }
    }

    const int r0 = row0 + w * 16 + (lane >> 2);
    const int r1 = r0 + 8;
    #pragma unroll
    for (int nt = 0; nt < 20; nt++) {
        const int c = nt * 8 + 2 * (lane & 3);
        uint32_t p0, p1;
        asm("cvt.rn.bf16x2.f32 %0, %1, %2;" : "=r"(p0) : "f"(C[nt][1]), "f"(C[nt][0]));
        asm("cvt.rn.bf16x2.f32 %0, %1, %2;" : "=r"(p1) : "f"(C[nt][3]), "f"(C[nt][2]));
        if (c < 128) {
            *(uint32_t*)(g_V + (size_t)r0 * NC + c) = p0;
            *(uint32_t*)(g_V + (size_t)r1 * NC + c) = p1;
        } else if (c < 144) {
            const int d = c - 128;
            *(uint32_t*)(g_Kb + (size_t)r0 * ND + d) = p0;
            *(uint32_t*)(g_Kb + (size_t)r1 * ND + d) = p1;
        } else {
            const int d = c - 144;
            *(uint32_t*)(g_Qb + (size_t)r0 * ND + d) = p0;
            *(uint32_t*)(g_Qb + (size_t)r1 * ND + d) = p1;
        }
    }
}

// =====================================================================
// Flash attention (HMMA), 64-QUERY KEY-SPLIT CTAs, 2 CTAs/SM:
//   256 thr, 8 warps; warp = (rg = w&3 -> 16 query rows, kh = w>>2 -> 64-key
//   half of each 128-key tile). grid 64x4 = 256 CTAs -> 2 per SM (1 wave),
//   4 warps/SMSP with INDEPENDENT per-CTA barriers (desynchronized phases).
// Per-SM totals identical to R6 (no duplicated QK/exp/LDSM; only gmem V
// reads double: 2.1% -> ~4% DRAM, free). Regs ~115 (forced <=128 by
// __launch_bounds__(256,2)). Epilogue combines key halves via smem.
// =====================================================================
#define QKP 48                         // Q/K smem row pitch (bytes)
#define VP  272                        // V smem row pitch (bytes)
#define SM_Q  0                        // 64 x 48 = 3072
#define SM_K0 3072                     // 2 x 6144
#define SM_V0 15360                    // 2 x 34816
#define K_BUF_BYTES 6144
#define V_BUF_BYTES 34816
#define ATTN_SMEM_BYTES (SM_V0 + 2*V_BUF_BYTES)   // 84992
#define OXP 132                        // O-exchange row pitch (floats)

__global__ __launch_bounds__(256, 2) void attn_mma_kernel(
        const float* __restrict__ x,
        const float* __restrict__ gammap,
        float* __restrict__ out) {
    extern __shared__ char smem[];
    const uint32_t sb = smem_u32(smem);
    const int t = threadIdx.x;
    const int w = t >> 5, lane = t & 31;
    const int rg = w & 3;              // query-row group (16 rows)
    const int kh = w >> 2;             // key half (0: keys 0-63, 1: keys 64-127)
    const int b = blockIdx.y;
    const int m0 = blockIdx.x * 64;

    const __nv_bfloat16* qbase = g_Qb + (size_t)b * NN * ND;
    const __nv_bfloat16* kbase = g_Kb + (size_t)b * NN * ND;
    const __nv_bfloat16* vbase = g_V  + (size_t)b * NN * NC;

    // ---- stage Q tile [64 x 16] (pitch 48B) ----
    if (t < 128) {
        int r = t >> 1, c2 = t & 1;
        const uint4* src = (const uint4*)(qbase + (size_t)(m0 + r) * ND) + c2;
        *(uint4*)(smem + SM_Q + r * QKP + c2 * 16) = *src;
    }

    // ---- prefetch tile 0 (K+V) into buffer 0 ----
    {
        int r = t >> 1, c2 = t & 1;
        CP_ASYNC16(sb + SM_K0 + r * QKP + c2 * 16,
                   (const char*)(kbase) + (size_t)r * 32 + c2 * 16);
        #pragma unroll
        for (int i = 0; i < 8; i++) {
            int idx = t + i * 256;
            int row = idx >> 4, vch = idx & 15;
            CP_ASYNC16(sb + SM_V0 + row * VP + vch * 16,
                       (const char*)(vbase) + (size_t)row * 256 + vch * 16);
        }
    }
    CP_COMMIT();
    __syncthreads();

    // ---- Q A-fragment (constant for whole kernel) ----
    uint32_t qa[4];
    {
        uint32_t addr = sb + SM_Q + (uint32_t)(rg * 16 + (lane & 15)) * QKP
                      + (uint32_t)((lane >> 4) * 16);
        LDSM_X4(qa[0], qa[1], qa[2], qa[3], addr);
    }

    // per-lane ldmatrix fragment base offsets (+ key-half select)
    const uint32_t kfrag = (uint32_t)((lane & 7) + ((lane & 16) ? 8 : 0)) * QKP
                         + (uint32_t)((lane & 8) ? 16 : 0)
                         + (uint32_t)(kh * 64 * QKP);
    const uint32_t vfrag = (uint32_t)((lane & 7) + ((lane & 8) ? 8 : 0)) * VP
                         + (uint32_t)((lane & 16) ? 16 : 0)
                         + (uint32_t)(kh * 64 * VP);

    float O[16][4];
    #pragma unroll
    for (int i = 0; i < 16; i++)
        #pragma unroll
        for (int j = 0; j < 4; j++) O[i][j] = 0.f;
    float lsum0 = 0.f, lsum1 = 0.f;

    for (int tile = 0; tile < 32; ++tile) {
        // prefetch next tile into the other buffer
        if (tile < 31) {
            const int nb_ = (tile + 1) & 1;
            const size_t n0n = (size_t)(tile + 1) * 128;
            int r = t >> 1, c2 = t & 1;
            CP_ASYNC16(sb + SM_K0 + nb_ * K_BUF_BYTES + r * QKP + c2 * 16,
                       (const char*)(kbase) + (n0n + r) * 32 + c2 * 16);
            #pragma unroll
            for (int i = 0; i < 8; i++) {
                int idx = t + i * 256;
                int row = idx >> 4, vch = idx & 15;
                CP_ASYNC16(sb + SM_V0 + nb_ * V_BUF_BYTES + row * VP + vch * 16,
                           (const char*)(vbase) + (n0n + row) * 256 + vch * 16);
            }
            CP_COMMIT();
            CP_WAIT1();
        } else {
            CP_WAIT0();
        }
        __syncthreads();

        const uint32_t kbuf = sb + SM_K0 + (tile & 1) * K_BUF_BYTES;
        const uint32_t vbuf = sb + SM_V0 + (tile & 1) * V_BUF_BYTES;

        // ---- QK + exp for this warp's 64-key half (4 n8-pairs) ----
        uint32_t pa[4][4];             // static indices only
        #pragma unroll
        for (int kk = 0; kk < 4; kk++) {
            float S0[4] = {0.f, 0.f, 0.f, 0.f};
            float S1[4] = {0.f, 0.f, 0.f, 0.f};
            uint32_t kb0, kb1, kb2, kb3;
            LDSM_X4(kb0, kb1, kb2, kb3, kbuf + kfrag + (uint32_t)kk * (16 * QKP));
            mma16816(S0, qa, kb0, kb1);
            mma16816(S1, qa, kb2, kb3);
            float e0 = __expf(S0[0]), e1 = __expf(S0[1]);
            float e2 = __expf(S0[2]), e3 = __expf(S0[3]);
            float e4 = __expf(S1[0]), e5 = __expf(S1[1]);
            float e6 = __expf(S1[2]), e7 = __expf(S1[3]);
            lsum0 += e0 + e1 + e4 + e5;
            lsum1 += e2 + e3 + e6 + e7;
            asm("cvt.rn.bf16x2.f32 %0, %1, %2;" : "=r"(pa[kk][0]) : "f"(e1), "f"(e0));
            asm("cvt.rn.bf16x2.f32 %0, %1, %2;" : "=r"(pa[kk][1]) : "f"(e3), "f"(e2));
            asm("cvt.rn.bf16x2.f32 %0, %1, %2;" : "=r"(pa[kk][2]) : "f"(e5), "f"(e4));
            asm("cvt.rn.bf16x2.f32 %0, %1, %2;" : "=r"(pa[kk][3]) : "f"(e7), "f"(e6));
        }

        // ---- O += P . V over this warp's 64-key half (all 128 cols) ----
        #pragma unroll
        for (int kk = 0; kk < 4; kk++) {
            #pragma unroll
            for (int cp = 0; cp < 8; cp++) {
                uint32_t vb0, vb1, vb2, vb3;
                LDSM_X4_T(vb0, vb1, vb2, vb3,
                          vbuf + vfrag + (uint32_t)kk * (16 * VP) + (uint32_t)cp * 32);
                mma16816(O[2*cp],     pa[kk], vb0, vb1);
                mma16816(O[2*cp + 1], pa[kk], vb2, vb3);
            }
        }
        __syncthreads();
    }

    // ---- combine key halves ----
    lsum0 += __shfl_xor_sync(0xffffffffu, lsum0, 1);
    lsum0 += __shfl_xor_sync(0xffffffffu, lsum0, 2);
    lsum1 += __shfl_xor_sync(0xffffffffu, lsum1, 1);
    lsum1 += __shfl_xor_sync(0xffffffffu, lsum1, 2);

    float* lsx = (float*)smem;                     // reuse Q area (256 B)
    float* OX  = (float*)(smem + SM_K0);           // reuse K+V areas (33.8 KB)
    const int lr0 = rg * 16 + (lane >> 2);         // local row 0..63
    const int lr1 = lr0 + 8;

    if (kh == 1) {
        lsx[lr0] = lsum0;
        lsx[lr1] = lsum1;
        #pragma unroll
        for (int nt = 0; nt < 16; nt++) {
            const int c = nt * 8 + 2 * (lane & 3);
            *(float2*)&OX[lr0 * OXP + c] = make_float2(O[nt][0], O[nt][1]);
            *(float2*)&OX[lr1 * OXP + c] = make_float2(O[nt][2], O[nt][3]);
        }
    }
    __syncthreads();

    if (kh == 0) {
        const float inv0 = 1.0f / (lsum0 + lsx[lr0]);
        const float inv1 = 1.0f / (lsum1 + lsx[lr1]);
        const float gamma = *gammap;
        const int r0 = m0 + lr0;
        const int r1 = m0 + lr1;
        const size_t bbase = (size_t)b * (NN * NC);
        #pragma unroll
        for (int nt = 0; nt < 16; nt++) {
            const int c = nt * 8 + 2 * (lane & 3);
            float2 b0 = *(float2*)&OX[lr0 * OXP + c];
            float2 b1 = *(float2*)&OX[lr1 * OXP + c];
            const size_t i00 = bbase + (size_t)c * NN + r0;
            out[i00]      = gamma * ((O[nt][0] + b0.x) * inv0) + x[i00];
            out[i00 + NN] = gamma * ((O[nt][1] + b0.y) * inv0) + x[i00 + NN];
            const size_t i10 = bbase + (size_t)c * NN + r1;
            out[i10]      = gamma * ((O[nt][2] + b1.x) * inv1) + x[i10];
            out[i10 + NN] = gamma * ((O[nt][3] + b1.y) * inv1) + x[i10 + NN];
        }
    }
}

// =====================================================================
extern "C" void kernel_launch(void* const* d_in, const int* in_sizes, int n_in,
                              void* d_out, int out_size) {
    (void)in_sizes; (void)n_in; (void)out_size;
    const float* x     = (const float*)d_in[0];
    const float* Wq    = (const float*)d_in[1];
    const float* Wk    = (const float*)d_in[2];
    const float* Wv    = (const float*)d_in[3];
    const float* gamma = (const float*)d_in[4];
    float* out = (float*)d_out;

    cudaFuncSetAttribute((const void*)proj_mma_kernel,
                         cudaFuncAttributeMaxDynamicSharedMemorySize, PROJ_SMEM_BYTES);
    cudaFuncSetAttribute((const void*)attn_mma_kernel,
                         cudaFuncAttributeMaxDynamicSharedMemorySize, ATTN_SMEM_BYTES);

    proj_mma_kernel<<<128, 256, PROJ_SMEM_BYTES>>>(x, Wq, Wk, Wv);
    attn_mma_kernel<<<dim3(64, 4), 256, ATTN_SMEM_BYTES>>>(x, gamma, out);
}

// round 15
// speedup vs baseline: 1.5715x; 1.2361x over previous
#include <cuda_runtime.h>
#include <cuda_bf16.h>
#include <cstdint>

// Problem constants
#define NB  4        // batch
#define NN  4096     // sequence (64*64)
#define NC  128      // channels
#define ND  16       // qk head dim

__device__ __forceinline__ uint32_t smem_u32(const void* p) {
    uint32_t a;
    asm("{ .reg .u64 tmp; cvta.to.shared.u64 tmp, %1; cvt.u32.u64 %0, tmp; }"
        : "=r"(a) : "l"(p));
    return a;
}

// ---- warp MMA primitives (plain PTX, valid on sm_100 non-a) ----
__device__ __forceinline__ void mma16816(float* c, const uint32_t* a,
                                         uint32_t b0, uint32_t b1) {
    asm volatile(
        "mma.sync.aligned.m16n8k16.row.col.f32.bf16.bf16.f32 "
        "{%0,%1,%2,%3}, {%4,%5,%6,%7}, {%8,%9}, {%0,%1,%2,%3};"
        : "+f"(c[0]), "+f"(c[1]), "+f"(c[2]), "+f"(c[3])
        : "r"(a[0]), "r"(a[1]), "r"(a[2]), "r"(a[3]), "r"(b0), "r"(b1));
}
#define LDSM_X4(r0,r1,r2,r3,addr) \
    asm volatile("ldmatrix.sync.aligned.m8n8.x4.shared.b16 {%0,%1,%2,%3}, [%4];" \
        : "=r"(r0), "=r"(r1), "=r"(r2), "=r"(r3) : "r"(addr))
#define LDSM_X4_T(r0,r1,r2,r3,addr) \
    asm volatile("ldmatrix.sync.aligned.m8n8.x4.trans.shared.b16 {%0,%1,%2,%3}, [%4];" \
        : "=r"(r0), "=r"(r1), "=r"(r2), "=r"(r3) : "r"(addr))

#define CP_ASYNC16(dst, src) \
    asm volatile("cp.async.cg.shared.global [%0], [%1], 16;" :: "r"(dst), "l"(src) : "memory")
#define CP_COMMIT() asm volatile("cp.async.commit_group;" ::: "memory")
#define CP_WAIT1()  asm volatile("cp.async.wait_group 1;" ::: "memory")
#define CP_WAIT0()  asm volatile("cp.async.wait_group 0;" ::: "memory")

// =====================================================================
// Device scratch
// =====================================================================
__device__ __nv_bfloat16 g_Qb[NB * NN * ND];            // queries = x @ Wk (bf16)
__device__ __nv_bfloat16 g_Kb[NB * NN * ND];            // keys    = x @ Wq (bf16)
__device__ __nv_bfloat16 g_V [(size_t)NB * NN * NC];    // values  = x @ Wv (bf16) [b][n][c]

// =====================================================================
// Projection GEMM (HMMA): [16384 x 128] x [128 x 160] -> V | Kb | Qb
// (round-6 version — measured ~1us)
// =====================================================================
#define PJP 272
#define WP  336
#define PSM_X 0
#define PSM_W (128 * PJP)
#define PROJ_SMEM_BYTES (PSM_W + 128 * WP)      // 77824

__global__ __launch_bounds__(256, 1) void proj_mma_kernel(
        const float* __restrict__ x,
        const float* __restrict__ Wq,
        const float* __restrict__ Wk,
        const float* __restrict__ Wv) {
    extern __shared__ char smem[];
    const uint32_t sb = smem_u32(smem);
    const int t = threadIdx.x;
    const int w = t >> 5, lane = t & 31;
    const int row0 = blockIdx.x * 128;

    {
        const float4* wv4 = (const float4*)Wv;
        #pragma unroll
        for (int i = 0; i < 16; i++) {
            int idx = t + i * 256;
            int c = idx >> 5, e4 = idx & 31;
            float4 v = wv4[idx];
            uint2 p;
            asm("cvt.rn.bf16x2.f32 %0, %1, %2;" : "=r"(p.x) : "f"(v.y), "f"(v.x));
            asm("cvt.rn.bf16x2.f32 %0, %1, %2;" : "=r"(p.y) : "f"(v.w), "f"(v.z));
            *(uint2*)(smem + PSM_W + c * WP + e4 * 8) = p;
        }
        const float4* wq4 = (const float4*)Wq;
        const float4* wk4 = (const float4*)Wk;
        #pragma unroll
        for (int i = 0; i < 2; i++) {
            int idx = t + i * 256;
            int c = idx >> 2, d4 = idx & 3;
            float4 q = wq4[idx];
            uint2 p;
            asm("cvt.rn.bf16x2.f32 %0, %1, %2;" : "=r"(p.x) : "f"(q.y), "f"(q.x));
            asm("cvt.rn.bf16x2.f32 %0, %1, %2;" : "=r"(p.y) : "f"(q.w), "f"(q.z));
            *(uint2*)(smem + PSM_W + c * WP + 256 + d4 * 8) = p;
            float4 k = wk4[idx];
            asm("cvt.rn.bf16x2.f32 %0, %1, %2;" : "=r"(p.x) : "f"(k.y), "f"(k.x));
            asm("cvt.rn.bf16x2.f32 %0, %1, %2;" : "=r"(p.y) : "f"(k.w), "f"(k.z));
            *(uint2*)(smem + PSM_W + c * WP + 288 + d4 * 8) = p;
        }
    }
    {
        const float4* src = (const float4*)(x + (size_t)row0 * NC);
        #pragma unroll
        for (int i = 0; i < 16; i++) {
            int idx = t + i * 256;
            int r = idx >> 5, ch = idx & 31;
            float4 v = src[idx];
            uint2 p;
            asm("cvt.rn.bf16x2.f32 %0, %1, %2;" : "=r"(p.x) : "f"(v.y), "f"(v.x));
            asm("cvt.rn.bf16x2.f32 %0, %1, %2;" : "=r"(p.y) : "f"(v.w), "f"(v.z));
            *(uint2*)(smem + PSM_X + r * PJP + ch * 8) = p;
        }
    }
    __syncthreads();

    float C[20][4];
    #pragma unroll
    for (int i = 0; i < 20; i++)
        #pragma unroll
        for (int j = 0; j < 4; j++) C[i][j] = 0.f;

    const uint32_t a_base = sb + PSM_X + (uint32_t)(w * 16 + (lane & 15)) * PJP
                          + (uint32_t)((lane >> 4) * 16);
    const uint32_t b_base = sb + PSM_W
                          + (uint32_t)((lane & 7) + ((lane & 8) ? 8 : 0)) * WP
                          + (uint32_t)((lane & 16) ? 16 : 0);

    #pragma unroll
    for (int k = 0; k < 8; k++) {
        uint32_t a[4];
        LDSM_X4(a[0], a[1], a[2], a[3], a_base + (uint32_t)k * 32);
        const uint32_t bk = b_base + (uint32_t)k * (16 * WP);
        #pragma unroll
        for (int np = 0; np < 10; np++) {
            uint32_t b0, b1, b2, b3;
            LDSM_X4_T(b0, b1, b2, b3, bk + (uint32_t)np * 32);
            mma16816(C[2*np],     a, b0, b1);
            mma16816(C[2*np + 1], a, b2, b3);
        }
    }

    const int r0 = row0 + w * 16 + (lane >> 2);
    const int r1 = r0 + 8;
    #pragma unroll
    for (int nt = 0; nt < 20; nt++) {
        const int c = nt * 8 + 2 * (lane & 3);
        uint32_t p0, p1;
        asm("cvt.rn.bf16x2.f32 %0, %1, %2;" : "=r"(p0) : "f"(C[nt][1]), "f"(C[nt][0]));
        asm("cvt.rn.bf16x2.f32 %0, %1, %2;" : "=r"(p1) : "f"(C[nt][3]), "f"(C[nt][2]));
        if (c < 128) {
            *(uint32_t*)(g_V + (size_t)r0 * NC + c) = p0;
            *(uint32_t*)(g_V + (size_t)r1 * NC + c) = p1;
        } else if (c < 144) {
            const int d = c - 128;
            *(uint32_t*)(g_Kb + (size_t)r0 * ND + d) = p0;
            *(uint32_t*)(g_Kb + (size_t)r1 * ND + d) = p1;
        } else {
            const int d = c - 144;
            *(uint32_t*)(g_Qb + (size_t)r0 * ND + d) = p0;
            *(uint32_t*)(g_Qb + (size_t)r1 * ND + d) = p1;
        }
    }
}

// =====================================================================
// Flash attention via mma.sync (HMMA). CTA = 128 queries (8 warps x 16 rows),
// 32 key-tiles of 128, cp.async double-buffered K/V.
// PV loop: cp OUTER / kk INNER (round-4 measured-fastest order).
// Final-tile __syncthreads elided (nothing after it reads smem).
// =====================================================================
#define QKP 48                         // Q/K smem row pitch (bytes)
#define VP  272                        // V smem row pitch (bytes)
#define SM_Q  0
#define SM_K0 6144
#define SM_V0 18432
#define K_BUF_BYTES 6144
#define V_BUF_BYTES 34816
#define ATTN_SMEM_BYTES (SM_V0 + 2*V_BUF_BYTES)   // 88064

__global__ __launch_bounds__(256, 1) void attn_mma_kernel(
        const float* __restrict__ x,
        const float* __restrict__ gammap,
        float* __restrict__ out) {
    extern __shared__ char smem[];
    const uint32_t sb = smem_u32(smem);
    const int t = threadIdx.x;
    const int w = t >> 5, lane = t & 31;
    const int b = blockIdx.y;
    const int m0 = blockIdx.x * 128;

    const __nv_bfloat16* qbase = g_Qb + (size_t)b * NN * ND;
    const __nv_bfloat16* kbase = g_Kb + (size_t)b * NN * ND;
    const __nv_bfloat16* vbase = g_V  + (size_t)b * NN * NC;

    // ---- stage Q tile [128 x 16] (pitch 48B) ----
    {
        int r = t >> 1, ch = t & 1;
        const uint4* src = (const uint4*)(qbase + (size_t)(m0 + r) * ND) + ch;
        *(uint4*)(smem + SM_Q + r * QKP + ch * 16) = *src;
    }

    // ---- prefetch tile 0 (K+V) into buffer 0 ----
    {
        int r = t >> 1, ch = t & 1;
        CP_ASYNC16(sb + SM_K0 + r * QKP + ch * 16,
                   (const char*)(kbase) + (size_t)r * 32 + ch * 16);
        #pragma unroll
        for (int i = 0; i < 8; i++) {
            int idx = t + i * 256;
            int row = idx >> 4, vch = idx & 15;
            CP_ASYNC16(sb + SM_V0 + row * VP + vch * 16,
                       (const char*)(vbase) + (size_t)row * 256 + vch * 16);
        }
    }
    CP_COMMIT();
    __syncthreads();

    // ---- Q A-fragment (constant for whole kernel) ----
    uint32_t qa[4];
    {
        uint32_t addr = sb + SM_Q + (uint32_t)(w * 16 + (lane & 15)) * QKP
                      + (uint32_t)((lane >> 4) * 16);
        LDSM_X4(qa[0], qa[1], qa[2], qa[3], addr);
    }

    // per-lane ldmatrix fragment base offsets
    const uint32_t kfrag = (uint32_t)((lane & 7) + ((lane & 16) ? 8 : 0)) * QKP
                         + (uint32_t)((lane & 8) ? 16 : 0);
    const uint32_t vfrag = (uint32_t)((lane & 7) + ((lane & 8) ? 8 : 0)) * VP
                         + (uint32_t)((lane & 16) ? 16 : 0);

    float O[16][4];
    #pragma unroll
    for (int i = 0; i < 16; i++)
        #pragma unroll
        for (int j = 0; j < 4; j++) O[i][j] = 0.f;
    float lsum0 = 0.f, lsum1 = 0.f;

    for (int tile = 0; tile < 32; ++tile) {
        // prefetch next tile into the other buffer
        if (tile < 31) {
            const int nb_ = (tile + 1) & 1;
            const size_t n0n = (size_t)(tile + 1) * 128;
            int r = t >> 1, ch = t & 1;
            CP_ASYNC16(sb + SM_K0 + nb_ * K_BUF_BYTES + r * QKP + ch * 16,
                       (const char*)(kbase) + (n0n + r) * 32 + ch * 16);
            #pragma unroll
            for (int i = 0; i < 8; i++) {
                int idx = t + i * 256;
                int row = idx >> 4, vch = idx & 15;
                CP_ASYNC16(sb + SM_V0 + nb_ * V_BUF_BYTES + row * VP + vch * 16,
                           (const char*)(vbase) + (n0n + row) * 256 + vch * 16);
            }
            CP_COMMIT();
            CP_WAIT1();
        } else {
            CP_WAIT0();
        }
        __syncthreads();

        const uint32_t kbuf = sb + SM_K0 + (tile & 1) * K_BUF_BYTES;
        const uint32_t vbuf = sb + SM_V0 + (tile & 1) * V_BUF_BYTES;

        // ---- S = Q . K^T : 16 n-tiles of 8 keys ----
        float S[16][4];
        #pragma unroll
        for (int i = 0; i < 16; i++)
            #pragma unroll
            for (int j = 0; j < 4; j++) S[i][j] = 0.f;
        #pragma unroll
        for (int ntp = 0; ntp < 8; ntp++) {
            uint32_t kb0, kb1, kb2, kb3;
            LDSM_X4(kb0, kb1, kb2, kb3, kbuf + kfrag + (uint32_t)ntp * (16 * QKP));
            mma16816(S[2*ntp],     qa, kb0, kb1);
            mma16816(S[2*ntp + 1], qa, kb2, kb3);
        }

        // ---- exp + pack into P A-fragments (register-level relayout) ----
        uint32_t pa[8][4];
        #pragma unroll
        for (int kk = 0; kk < 8; kk++) {
            float e0 = __expf(S[2*kk][0]),   e1 = __expf(S[2*kk][1]);
            float e2 = __expf(S[2*kk][2]),   e3 = __expf(S[2*kk][3]);
            float e4 = __expf(S[2*kk+1][0]), e5 = __expf(S[2*kk+1][1]);
            float e6 = __expf(S[2*kk+1][2]), e7 = __expf(S[2*kk+1][3]);
            lsum0 += e0 + e1 + e4 + e5;
            lsum1 += e2 + e3 + e6 + e7;
            asm("cvt.rn.bf16x2.f32 %0, %1, %2;" : "=r"(pa[kk][0]) : "f"(e1), "f"(e0));
            asm("cvt.rn.bf16x2.f32 %0, %1, %2;" : "=r"(pa[kk][1]) : "f"(e3), "f"(e2));
            asm("cvt.rn.bf16x2.f32 %0, %1, %2;" : "=r"(pa[kk][2]) : "f"(e5), "f"(e4));
            asm("cvt.rn.bf16x2.f32 %0, %1, %2;" : "=r"(pa[kk][3]) : "f"(e7), "f"(e6));
        }

        // ---- O += P . V : cp OUTER / kk INNER (round-4 measured-fastest) ----
        #pragma unroll
        for (int cp = 0; cp < 8; cp++) {
            const uint32_t vcol = vbuf + vfrag + (uint32_t)cp * 32;
            #pragma unroll
            for (int kk = 0; kk < 8; kk++) {
                uint32_t vb0, vb1, vb2, vb3;
                LDSM_X4_T(vb0, vb1, vb2, vb3, vcol + (uint32_t)kk * (16 * VP));
                mma16816(O[2*cp],     pa[kk], vb0, vb1);
                mma16816(O[2*cp + 1], pa[kk], vb2, vb3);
            }
        }
        // guard next iteration's prefetch overwrite; elide on the last tile
        if (tile < 31) __syncthreads();
    }

    // ---- softmax denominators: reduce across the 4-lane quad ----
    lsum0 += __shfl_xor_sync(0xffffffffu, lsum0, 1);
    lsum0 += __shfl_xor_sync(0xffffffffu, lsum0, 2);
    lsum1 += __shfl_xor_sync(0xffffffffu, lsum1, 1);
    lsum1 += __shfl_xor_sync(0xffffffffu, lsum1, 2);
    const float inv0 = 1.0f / lsum0;
    const float inv1 = 1.0f / lsum1;
    const float gamma = *gammap;

    // ---- write out[b, c*4096 + m] = gamma*O/lsum + x ----
    const int r0 = m0 + w * 16 + (lane >> 2);
    const int r1 = r0 + 8;
    const size_t bbase = (size_t)b * (NN * NC);
    #pragma unroll
    for (int nt = 0; nt < 16; nt++) {
        const int c = nt * 8 + 2 * (lane & 3);
        const size_t i00 = bbase + (size_t)c * NN + r0;
        out[i00]        = gamma * (O[nt][0] * inv0) + x[i00];
        out[i00 + NN]   = gamma * (O[nt][1] * inv0) + x[i00 + NN];
        const size_t i10 = bbase + (size_t)c * NN + r1;
        out[i10]        = gamma * (O[nt][2] * inv1) + x[i10];
        out[i10 + NN]   = gamma * (O[nt][3] * inv1) + x[i10 + NN];
    }
}

// =====================================================================
extern "C" void kernel_launch(void* const* d_in, const int* in_sizes, int n_in,
                              void* d_out, int out_size) {
    (void)in_sizes; (void)n_in; (void)out_size;
    const float* x     = (const float*)d_in[0];
    const float* Wq    = (const float*)d_in[1];
    const float* Wk    = (const float*)d_in[2];
    const float* Wv    = (const float*)d_in[3];
    const float* gamma = (const float*)d_in[4];
    float* out = (float*)d_out;

    cudaFuncSetAttribute((const void*)proj_mma_kernel,
                         cudaFuncAttributeMaxDynamicSharedMemorySize, PROJ_SMEM_BYTES);
    cudaFuncSetAttribute((const void*)attn_mma_kernel,
                         cudaFuncAttributeMaxDynamicSharedMemorySize, ATTN_SMEM_BYTES);

    proj_mma_kernel<<<128, 256, PROJ_SMEM_BYTES>>>(x, Wq, Wk, Wv);
    attn_mma_kernel<<<dim3(32, 4), 256, ATTN_SMEM_BYTES>>>(x, gamma, out);
}

// round 17
// speedup vs baseline: 1.5967x; 1.0160x over previous
#include <cuda_runtime.h>
#include <cuda_bf16.h>
#include <cstdint>

// Problem constants
#define NB  4        // batch
#define NN  4096     // sequence (64*64)
#define NC  128      // channels
#define ND  16       // qk head dim

__device__ __forceinline__ uint32_t smem_u32(const void* p) {
    uint32_t a;
    asm("{ .reg .u64 tmp; cvta.to.shared.u64 tmp, %1; cvt.u32.u64 %0, tmp; }"
        : "=r"(a) : "l"(p));
    return a;
}

// ---- warp MMA primitives (plain PTX, valid on sm_100 non-a) ----
__device__ __forceinline__ void mma16816(float* c, const uint32_t* a,
                                         uint32_t b0, uint32_t b1) {
    asm volatile(
        "mma.sync.aligned.m16n8k16.row.col.f32.bf16.bf16.f32 "
        "{%0,%1,%2,%3}, {%4,%5,%6,%7}, {%8,%9}, {%0,%1,%2,%3};"
        : "+f"(c[0]), "+f"(c[1]), "+f"(c[2]), "+f"(c[3])
        : "r"(a[0]), "r"(a[1]), "r"(a[2]), "r"(a[3]), "r"(b0), "r"(b1));
}
#define LDSM_X4(r0,r1,r2,r3,addr) \
    asm volatile("ldmatrix.sync.aligned.m8n8.x4.shared.b16 {%0,%1,%2,%3}, [%4];" \
        : "=r"(r0), "=r"(r1), "=r"(r2), "=r"(r3) : "r"(addr))
#define LDSM_X4_T(r0,r1,r2,r3,addr) \
    asm volatile("ldmatrix.sync.aligned.m8n8.x4.trans.shared.b16 {%0,%1,%2,%3}, [%4];" \
        : "=r"(r0), "=r"(r1), "=r"(r2), "=r"(r3) : "r"(addr))

#define CP_ASYNC16(dst, src) \
    asm volatile("cp.async.cg.shared.global [%0], [%1], 16;" :: "r"(dst), "l"(src) : "memory")
#define CP_COMMIT() asm volatile("cp.async.commit_group;" ::: "memory")
#define CP_WAIT1()  asm volatile("cp.async.wait_group 1;" ::: "memory")
#define CP_WAIT0()  asm volatile("cp.async.wait_group 0;" ::: "memory")

// =====================================================================
// Device scratch
// =====================================================================
__device__ __nv_bfloat16 g_Qb[NB * NN * ND];            // queries = x @ Wk (bf16)
__device__ __nv_bfloat16 g_Kb[NB * NN * ND];            // keys    = x @ Wq (bf16)
__device__ __nv_bfloat16 g_V [(size_t)NB * NN * NC];    // values  = x @ Wv (bf16) [b][n][c]

// =====================================================================
// Projection GEMM (HMMA): [16384 x 128] x [128 x 160] -> V | Kb | Qb
// =====================================================================
#define PJP 272
#define WP  336
#define PSM_X 0
#define PSM_W (128 * PJP)
#define PROJ_SMEM_BYTES (PSM_W + 128 * WP)      // 77824

__global__ __launch_bounds__(256, 1) void proj_mma_kernel(
        const float* __restrict__ x,
        const float* __restrict__ Wq,
        const float* __restrict__ Wk,
        const float* __restrict__ Wv) {
    extern __shared__ char smem[];
    const uint32_t sb = smem_u32(smem);
    const int t = threadIdx.x;
    const int w = t >> 5;
    const int lane = t & 31;
    const int row0 = blockIdx.x * 128;

    {
        const float4* wv4 = (const float4*)Wv;
        #pragma unroll
        for (int i = 0; i < 16; i++) {
            const int idx = t + i * 256;
            const int c = idx >> 5, e4 = idx & 31;
            float4 v = wv4[idx];
            uint2 p;
            asm("cvt.rn.bf16x2.f32 %0, %1, %2;" : "=r"(p.x) : "f"(v.y), "f"(v.x));
            asm("cvt.rn.bf16x2.f32 %0, %1, %2;" : "=r"(p.y) : "f"(v.w), "f"(v.z));
            *(uint2*)(smem + PSM_W + c * WP + e4 * 8) = p;
        }
        const float4* wq4 = (const float4*)Wq;
        const float4* wk4 = (const float4*)Wk;
        #pragma unroll
        for (int i = 0; i < 2; i++) {
            const int idx = t + i * 256;
            const int c = idx >> 2, d4 = idx & 3;
            float4 q = wq4[idx];
            uint2 p;
            asm("cvt.rn.bf16x2.f32 %0, %1, %2;" : "=r"(p.x) : "f"(q.y), "f"(q.x));
            asm("cvt.rn.bf16x2.f32 %0, %1, %2;" : "=r"(p.y) : "f"(q.w), "f"(q.z));
            *(uint2*)(smem + PSM_W + c * WP + 256 + d4 * 8) = p;
            float4 k = wk4[idx];
            asm("cvt.rn.bf16x2.f32 %0, %1, %2;" : "=r"(p.x) : "f"(k.y), "f"(k.x));
            asm("cvt.rn.bf16x2.f32 %0, %1, %2;" : "=r"(p.y) : "f"(k.w), "f"(k.z));
            *(uint2*)(smem + PSM_W + c * WP + 288 + d4 * 8) = p;
        }
    }
    {
        const float4* src = (const float4*)(x + (size_t)row0 * NC);
        #pragma unroll
        for (int i = 0; i < 16; i++) {
            const int idx = t + i * 256;
            const int r = idx >> 5, ch = idx & 31;
            float4 v = src[idx];
            uint2 p;
            asm("cvt.rn.bf16x2.f32 %0, %1, %2;" : "=r"(p.x) : "f"(v.y), "f"(v.x));
            asm("cvt.rn.bf16x2.f32 %0, %1, %2;" : "=r"(p.y) : "f"(v.w), "f"(v.z));
            *(uint2*)(smem + PSM_X + r * PJP + ch * 8) = p;
        }
    }
    __syncthreads();

    float C[20][4];
    #pragma unroll
    for (int i = 0; i < 20; i++) {
        C[i][0] = 0.f; C[i][1] = 0.f; C[i][2] = 0.f; C[i][3] = 0.f;
    }

    const uint32_t a_base = sb + PSM_X + (uint32_t)(w * 16 + (lane & 15)) * PJP
                          + (uint32_t)((lane >> 4) * 16);
    const uint32_t b_base = sb + PSM_W
                          + (uint32_t)((lane & 7) + ((lane & 8) ? 8 : 0)) * WP
                          + (uint32_t)((lane & 16) ? 16 : 0);

    #pragma unroll
    for (int k = 0; k < 8; k++) {
        uint32_t a[4];
        LDSM_X4(a[0], a[1], a[2], a[3], a_base + (uint32_t)k * 32);
        const uint32_t bk = b_base + (uint32_t)k * (16 * WP);
        #pragma unroll
        for (int np = 0; np < 10; np++) {
            uint32_t b0, b1, b2, b3;
            LDSM_X4_T(b0, b1, b2, b3, bk + (uint32_t)np * 32);
            mma16816(C[2*np],     a, b0, b1);
            mma16816(C[2*np + 1], a, b2, b3);
        }
    }

    const int r0 = row0 + w * 16 + (lane >> 2);
    const int r1 = r0 + 8;
    #pragma unroll
    for (int nt = 0; nt < 20; nt++) {
        const int c = nt * 8 + 2 * (lane & 3);
        uint32_t p0, p1;
        asm("cvt.rn.bf16x2.f32 %0, %1, %2;" : "=r"(p0) : "f"(C[nt][1]), "f"(C[nt][0]));
        asm("cvt.rn.bf16x2.f32 %0, %1, %2;" : "=r"(p1) : "f"(C[nt][3]), "f"(C[nt][2]));
        if (c < 128) {
            *(uint32_t*)(g_V + (size_t)r0 * NC + c) = p0;
            *(uint32_t*)(g_V + (size_t)r1 * NC + c) = p1;
        } else if (c < 144) {
            const int d = c - 128;
            *(uint32_t*)(g_Kb + (size_t)r0 * ND + d) = p0;
            *(uint32_t*)(g_Kb + (size_t)r1 * ND + d) = p1;
        } else {
            const int d = c - 144;
            *(uint32_t*)(g_Qb + (size_t)r0 * ND + d) = p0;
            *(uint32_t*)(g_Qb + (size_t)r1 * ND + d) = p1;
        }
    }
}

// =====================================================================
// Flash attention via mma.sync. CTA = 128 queries (8 warps x 16 rows),
// 32 key-tiles of 128. Triple-buffered K/V ring with a single
// __syncthreads per tile (the write at tile t targets ring slot
// (t+1)%3, last read in tile t-2, which every warp finished before the
// t-1 barrier that precedes this write — WAR-safe without a bottom
// barrier). PV loop: cp OUTER / kk INNER.
// =====================================================================
#define QKP 48                         // Q/K smem row pitch (bytes)
#define VP  272                        // V smem row pitch (bytes)
#define SM_Q  0
#define SM_K0 6144
#define SM_V0 24576                    // after the 3 K ring slots
#define K_BUF_BYTES 6144
#define V_BUF_BYTES 34816
#define ATTN_SMEM_BYTES (SM_V0 + 3*V_BUF_BYTES)   // 129024

__global__ __launch_bounds__(256, 1) void attn_mma_kernel(
        const float* __restrict__ x,
        const float* __restrict__ gammap,
        float* __restrict__ out) {
    extern __shared__ char smem[];
    const uint32_t sb = smem_u32(smem);
    const int t = threadIdx.x;
    const int w = t >> 5;
    const int lane = t & 31;
    const int b = blockIdx.y;
    const int m0 = blockIdx.x * 128;

    const __nv_bfloat16* qbase = g_Qb + (size_t)b * NN * ND;
    const __nv_bfloat16* kbase = g_Kb + (size_t)b * NN * ND;
    const __nv_bfloat16* vbase = g_V  + (size_t)b * NN * NC;

    const int ldr = t >> 1;            // staging row (0..127)
    const int ldc = t & 1;             // staging 16B chunk within row

    // ---- stage Q tile [128 x 16] (pitch 48B) ----
    {
        const uint4* src = (const uint4*)(qbase + (size_t)(m0 + ldr) * ND) + ldc;
        *(uint4*)(smem + SM_Q + ldr * QKP + ldc * 16) = *src;
    }

    // ---- prefetch tile 0 (K+V) into ring slot 0 ----
    {
        CP_ASYNC16(sb + SM_K0 + ldr * QKP + ldc * 16,
                   (const char*)(kbase) + (size_t)ldr * 32 + ldc * 16);
        #pragma unroll
        for (int i = 0; i < 8; i++) {
            const int idx = t + i * 256;
            const int row = idx >> 4, vch = idx & 15;
            CP_ASYNC16(sb + SM_V0 + row * VP + vch * 16,
                       (const char*)(vbase) + (size_t)row * 256 + vch * 16);
        }
    }
    CP_COMMIT();
    __syncthreads();

    // ---- Q A-fragment (constant for whole kernel) ----
    uint32_t qa[4];
    {
        const uint32_t addr = sb + SM_Q + (uint32_t)(w * 16 + (lane & 15)) * QKP
                            + (uint32_t)((lane >> 4) * 16);
        LDSM_X4(qa[0], qa[1], qa[2], qa[3], addr);
    }

    // per-lane ldmatrix fragment base offsets
    const uint32_t kfrag = (uint32_t)((lane & 7) + ((lane & 16) ? 8 : 0)) * QKP
                         + (uint32_t)((lane & 8) ? 16 : 0);
    const uint32_t vfrag = (uint32_t)((lane & 7) + ((lane & 8) ? 8 : 0)) * VP
                         + (uint32_t)((lane & 16) ? 16 : 0);

    float O[16][4];
    #pragma unroll
    for (int i = 0; i < 16; i++) {
        O[i][0] = 0.f; O[i][1] = 0.f; O[i][2] = 0.f; O[i][3] = 0.f;
    }
    float lsum0 = 0.f, lsum1 = 0.f;

    int rd = 0;                        // ring slot being consumed (tile % 3)
    for (int tile = 0; tile < 32; ++tile) {
        const int wr = (rd + 1 == 3) ? 0 : rd + 1;   // slot for tile+1
        // prefetch next tile into slot wr (last read in tile-2; WAR-safe)
        if (tile != 31) {
            const size_t n0n = (size_t)(tile + 1) * 128;
            CP_ASYNC16(sb + SM_K0 + wr * K_BUF_BYTES + ldr * QKP + ldc * 16,
                       (const char*)(kbase) + (n0n + ldr) * 32 + ldc * 16);
            #pragma unroll
            for (int i = 0; i < 8; i++) {
                const int idx = t + i * 256;
                const int row = idx >> 4, vch = idx & 15;
                CP_ASYNC16(sb + SM_V0 + wr * V_BUF_BYTES + row * VP + vch * 16,
                           (const char*)(vbase) + (n0n + row) * 256 + vch * 16);
            }
            CP_COMMIT();
            CP_WAIT1();
        } else {
            CP_WAIT0();
        }
        __syncthreads();               // sole barrier of the tile

        const uint32_t kbuf = sb + SM_K0 + rd * K_BUF_BYTES;
        const uint32_t vbuf = sb + SM_V0 + rd * V_BUF_BYTES;

        // ---- S = Q . K^T : 16 n-tiles of 8 keys ----
        float S[16][4];
        #pragma unroll
        for (int i = 0; i < 16; i++) {
            S[i][0] = 0.f; S[i][1] = 0.f; S[i][2] = 0.f; S[i][3] = 0.f;
        }
        #pragma unroll
        for (int ntp = 0; ntp < 8; ntp++) {
            uint32_t kb0, kb1, kb2, kb3;
            LDSM_X4(kb0, kb1, kb2, kb3, kbuf + kfrag + (uint32_t)ntp * (16 * QKP));
            mma16816(S[2*ntp],     qa, kb0, kb1);
            mma16816(S[2*ntp + 1], qa, kb2, kb3);
        }

        // ---- exp + pack into P A-fragments (register-level relayout) ----
        uint32_t pa[8][4];
        #pragma unroll
        for (int kk = 0; kk < 8; kk++) {
            const float e0 = __expf(S[2*kk][0]),   e1 = __expf(S[2*kk][1]);
            const float e2 = __expf(S[2*kk][2]),   e3 = __expf(S[2*kk][3]);
            const float e4 = __expf(S[2*kk+1][0]), e5 = __expf(S[2*kk+1][1]);
            const float e6 = __expf(S[2*kk+1][2]), e7 = __expf(S[2*kk+1][3]);
            lsum0 += e0 + e1 + e4 + e5;
            lsum1 += e2 + e3 + e6 + e7;
            asm("cvt.rn.bf16x2.f32 %0, %1, %2;" : "=r"(pa[kk][0]) : "f"(e1), "f"(e0));
            asm("cvt.rn.bf16x2.f32 %0, %1, %2;" : "=r"(pa[kk][1]) : "f"(e3), "f"(e2));
            asm("cvt.rn.bf16x2.f32 %0, %1, %2;" : "=r"(pa[kk][2]) : "f"(e5), "f"(e4));
            asm("cvt.rn.bf16x2.f32 %0, %1, %2;" : "=r"(pa[kk][3]) : "f"(e7), "f"(e6));
        }

        // ---- O += P . V : cp OUTER / kk INNER ----
        #pragma unroll
        for (int cp = 0; cp < 8; cp++) {
            const uint32_t vcol = vbuf + vfrag + (uint32_t)cp * 32;
            #pragma unroll
            for (int kk = 0; kk < 8; kk++) {
                uint32_t vb0, vb1, vb2, vb3;
                LDSM_X4_T(vb0, vb1, vb2, vb3, vcol + (uint32_t)kk * (16 * VP));
                mma16816(O[2*cp],     pa[kk], vb0, vb1);
                mma16816(O[2*cp + 1], pa[kk], vb2, vb3);
            }
        }
        rd = wr;                       // advance ring
    }

    // ---- softmax denominators: reduce across the 4-lane quad ----
    lsum0 += __shfl_xor_sync(0xffffffffu, lsum0, 1);
    lsum0 += __shfl_xor_sync(0xffffffffu, lsum0, 2);
    lsum1 += __shfl_xor_sync(0xffffffffu, lsum1, 1);
    lsum1 += __shfl_xor_sync(0xffffffffu, lsum1, 2);
    const float inv0 = 1.0f / lsum0;
    const float inv1 = 1.0f / lsum1;
    const float gamma = *gammap;

    // ---- write out[b, c*4096 + m] = gamma*O/lsum + x ----
    const int r0 = m0 + w * 16 + (lane >> 2);
    const int r1 = r0 + 8;
    const size_t bbase = (size_t)b * (NN * NC);
    #pragma unroll
    for (int nt = 0; nt < 16; nt++) {
        const int c = nt * 8 + 2 * (lane & 3);
        const size_t i00 = bbase + (size_t)c * NN + r0;
        out[i00]        = gamma * (O[nt][0] * inv0) + x[i00];
        out[i00 + NN]   = gamma * (O[nt][1] * inv0) + x[i00 + NN];
        const size_t i10 = bbase + (size_t)c * NN + r1;
        out[i10]        = gamma * (O[nt][2] * inv1) + x[i10];
        out[i10 + NN]   = gamma * (O[nt][3] * inv1) + x[i10 + NN];
    }
}

// =====================================================================
extern "C" void kernel_launch(void* const* d_in, const int* in_sizes, int n_in,
                              void* d_out, int out_size) {
    (void)in_sizes; (void)n_in; (void)out_size;
    const float* x     = (const float*)d_in[0];
    const float* Wq    = (const float*)d_in[1];
    const float* Wk    = (const float*)d_in[2];
    const float* Wv    = (const float*)d_in[3];
    const float* gamma = (const float*)d_in[4];
    float* out = (float*)d_out;

    cudaFuncSetAttribute((const void*)proj_mma_kernel,
                         cudaFuncAttributeMaxDynamicSharedMemorySize, PROJ_SMEM_BYTES);
    cudaFuncSetAttribute((const void*)attn_mma_kernel,
                         cudaFuncAttributeMaxDynamicSharedMemorySize, ATTN_SMEM_BYTES);

    proj_mma_kernel<<<128, 256, PROJ_SMEM_BYTES>>>(x, Wq, Wk, Wv);
    attn_mma_kernel<<<dim3(32, 4), 256, ATTN_SMEM_BYTES>>>(x, gamma, out);
}